// round 3
// baseline (speedup 1.0000x reference)
#include <cuda_runtime.h>
#include <cuda_bf16.h>
#include <math.h>
#include <stdint.h>

#define N_NODES 10000
#define IN_DIMS 128
#define EMB 64
#define HID 64
#define NEG_SLOPE 0.2f
#define TILE 128
#define NT 79                 // ceil(N/128)
#define NPAD (NT*TILE)        // 10112
#define MAXEDGE 400000
#define KSPLIT 192            // hi|lo|hi  /  hi|hi|lo

// ---------------- scratch (no allocations allowed) ----------------
__device__ float    g_h[N_NODES*EMB];
__device__ float    g_hp[N_NODES*HID];
__device__ float    g_asrc[N_NODES];
__device__ float    g_adst[N_NODES];
__device__ unsigned g_mord[N_NODES];
__device__ float    g_denom[N_NODES];
__device__ float    g_eval[MAXEDGE + N_NODES];
__device__ float    g_w[MAXEDGE + N_NODES];
__device__ float    g_emb_acc[N_NODES*HID];
__device__ float    g_embP[NPAD*HID];
__device__ float    g_attr_part[IN_DIMS*EMB];
__device__ float    g_xa2[IN_DIMS*HID];
__device__ __align__(16) __nv_bfloat16 g_Abf[NPAD*KSPLIT];  // [hi|lo|hi]
__device__ __align__(16) __nv_bfloat16 g_Bbf[NPAD*KSPLIT];  // [hi|hi|lo]
// CSR scratch
__device__ int g_deg[N_NODES];
__device__ int g_cur[N_NODES];
__device__ int g_off[N_NODES + 1];
__device__ int2 g_epack[MAXEDGE + N_NODES];   // (src, edge-id)

// ---------------- helpers ----------------
__device__ __forceinline__ unsigned f2ord(float f) {
    unsigned b = __float_as_uint(f);
    return (b & 0x80000000u) ? ~b : (b | 0x80000000u);
}
__device__ __forceinline__ float ord2f(unsigned u) {
    unsigned b = (u & 0x80000000u) ? (u & 0x7fffffffu) : ~u;
    return __uint_as_float(b);
}

// ---------------- kernels ----------------
__global__ void k_zero() {
    int i = blockIdx.x * blockDim.x + threadIdx.x;
    int stride = gridDim.x * blockDim.x;
    for (int j = i; j < N_NODES; j += stride) {
        g_mord[j] = 0u; g_denom[j] = 0.f; g_deg[j] = 0; g_cur[j] = 0;
    }
    for (int j = i; j < IN_DIMS*EMB; j += stride) g_attr_part[j] = 0.f;
}

// h = relu(x @ W_stru + b_stru)   [N,128]x[128,64]
__global__ __launch_bounds__(256) void k_stru(const float* __restrict__ x,
                                              const float* __restrict__ W,
                                              const float* __restrict__ b) {
    __shared__ float Ws[IN_DIMS*EMB];
    __shared__ float xs[16*IN_DIMS];
    int t = threadIdx.x;
    for (int i = t; i < IN_DIMS*EMB; i += 256) Ws[i] = W[i];
    int nbase = blockIdx.x * 16;
    for (int i = t; i < 16*IN_DIMS; i += 256) {
        int n = nbase + i / IN_DIMS;
        xs[i] = (n < N_NODES) ? x[(size_t)n*IN_DIMS + (i % IN_DIMS)] : 0.f;
    }
    __syncthreads();
    int nl = t >> 4;
    int e0 = (t & 15) * 4;
    float a0=0.f, a1=0.f, a2=0.f, a3=0.f;
    #pragma unroll 4
    for (int k = 0; k < IN_DIMS; k++) {
        float xv = xs[nl*IN_DIMS + k];
        const float* w = &Ws[k*EMB + e0];
        a0 += xv*w[0]; a1 += xv*w[1]; a2 += xv*w[2]; a3 += xv*w[3];
    }
    int n = nbase + nl;
    if (n < N_NODES) {
        float* o = &g_h[n*EMB + e0];
        o[0] = fmaxf(a0 + b[e0+0], 0.f);
        o[1] = fmaxf(a1 + b[e0+1], 0.f);
        o[2] = fmaxf(a2 + b[e0+2], 0.f);
        o[3] = fmaxf(a3 + b[e0+3], 0.f);
    }
}

// hp = h @ W_gat   [N,64]x[64,64]
__global__ __launch_bounds__(256) void k_gatlin(const float* __restrict__ W) {
    __shared__ float Ws[EMB*HID];
    __shared__ float hs[16*EMB];
    int t = threadIdx.x;
    for (int i = t; i < EMB*HID; i += 256) Ws[i] = W[i];
    int nbase = blockIdx.x * 16;
    for (int i = t; i < 16*EMB; i += 256) {
        int n = nbase + i / EMB;
        hs[i] = (n < N_NODES) ? g_h[n*EMB + (i % EMB)] : 0.f;
    }
    __syncthreads();
    int nl = t >> 4;
    int e0 = (t & 15) * 4;
    float a0=0.f, a1=0.f, a2=0.f, a3=0.f;
    #pragma unroll 8
    for (int k = 0; k < EMB; k++) {
        float xv = hs[nl*EMB + k];
        const float* w = &Ws[k*HID + e0];
        a0 += xv*w[0]; a1 += xv*w[1]; a2 += xv*w[2]; a3 += xv*w[3];
    }
    int n = nbase + nl;
    if (n < N_NODES) {
        float* o = &g_hp[n*HID + e0];
        o[0]=a0; o[1]=a1; o[2]=a2; o[3]=a3;
    }
}

__global__ void k_att(const float* __restrict__ att_s, const float* __restrict__ att_d) {
    int warp = (blockIdx.x * blockDim.x + threadIdx.x) >> 5;
    int lane = threadIdx.x & 31;
    if (warp >= N_NODES) return;
    float h0 = g_hp[warp*HID + lane];
    float h1 = g_hp[warp*HID + 32 + lane];
    float s = h0*att_s[lane] + h1*att_s[32+lane];
    float d = h0*att_d[lane] + h1*att_d[32+lane];
    #pragma unroll
    for (int o = 16; o; o >>= 1) {
        s += __shfl_xor_sync(0xffffffffu, s, o);
        d += __shfl_xor_sync(0xffffffffu, d, o);
    }
    if (lane == 0) { g_asrc[warp] = s; g_adst[warp] = d; }
}

// per-edge: leaky-relu score, seg-max (ordered-uint atomic), degree count
__global__ void k_emax(const int* __restrict__ ei, int E) {
    int i = blockIdx.x * blockDim.x + threadIdx.x;
    if (i >= E + N_NODES) return;
    int s, d;
    if (i < E) { s = ei[i]; d = ei[E + i]; } else { s = d = i - E; }
    float e = g_asrc[s] + g_adst[d];
    e = (e > 0.f) ? e : NEG_SLOPE * e;
    g_eval[i] = e;
    atomicMax(&g_mord[d], f2ord(e));
    atomicAdd(&g_deg[d], 1);
}

// single-block exclusive scan of g_deg -> g_off
__global__ __launch_bounds__(1024) void k_scan() {
    __shared__ int tmp[1024];
    __shared__ int carry;
    int t = threadIdx.x;
    if (t == 0) carry = 0;
    __syncthreads();
    for (int base = 0; base < N_NODES; base += 1024) {
        int i = base + t;
        int v = (i < N_NODES) ? g_deg[i] : 0;
        tmp[t] = v;
        __syncthreads();
        for (int off = 1; off < 1024; off <<= 1) {
            int add = (t >= off) ? tmp[t - off] : 0;
            __syncthreads();
            tmp[t] += add;
            __syncthreads();
        }
        if (i < N_NODES) g_off[i + 1] = carry + tmp[t];
        __syncthreads();
        if (t == 1023) carry += tmp[1023];
        __syncthreads();
    }
    if (t == 0) g_off[0] = 0;
}

// exp weights + denom, and scatter edge into CSR slot
__global__ void k_eexp(const int* __restrict__ ei, int E) {
    int i = blockIdx.x * blockDim.x + threadIdx.x;
    if (i >= E + N_NODES) return;
    int s, d;
    if (i < E) { s = ei[i]; d = ei[E + i]; } else { s = d = i - E; }
    float m = ord2f(g_mord[d]);
    float w = __expf(g_eval[i] - m);
    g_w[i] = w;
    atomicAdd(&g_denom[d], w);
    int pos = g_off[d] + atomicAdd(&g_cur[d], 1);
    g_epack[pos] = make_int2(s, i);
}

// warp per dst: register accumulation, no float atomics
__global__ void k_aggr(int E) {
    int d = (blockIdx.x * blockDim.x + threadIdx.x) >> 5;
    int lane = threadIdx.x & 31;
    if (d >= N_NODES) return;
    int beg = g_off[d], end = g_off[d + 1];
    float inv = 1.f / g_denom[d];
    float a0 = 0.f, a1 = 0.f;
    for (int p = beg; p < end; p++) {
        int2 pk = g_epack[p];                 // broadcast load
        float coef = g_w[pk.y] * inv;         // broadcast load
        a0 += g_hp[pk.x*HID + lane]        * coef;
        a1 += g_hp[pk.x*HID + 32 + lane]   * coef;
    }
    g_emb_acc[d*HID + lane]      = a0;
    g_emb_acc[d*HID + 32 + lane] = a1;
}

// embP = emb_acc + b_gat, plus bf16 hi/lo split matrices for the MMA GEMM
__global__ void k_femb(const float* __restrict__ bg) {
    int i = blockIdx.x * blockDim.x + threadIdx.x;
    if (i >= NPAD*HID) return;
    int n = i >> 6, j = i & 63;
    float v = (n < N_NODES) ? (g_emb_acc[i] + bg[j]) : 0.f;
    g_embP[i] = v;
    __nv_bfloat16 hi = __float2bfloat16(v);
    __nv_bfloat16 lo = __float2bfloat16(v - __bfloat162float(hi));
    size_t base = (size_t)n * KSPLIT + j;
    g_Abf[base]       = hi;
    g_Abf[base + 64]  = lo;
    g_Abf[base + 128] = hi;
    g_Bbf[base]       = hi;
    g_Bbf[base + 64]  = hi;
    g_Bbf[base + 128] = lo;
}

// attr_part = x^T @ W_attr1  (split over 100 blocks)
__global__ __launch_bounds__(256) void k_attr1(const float* __restrict__ x,
                                               const float* __restrict__ W1) {
    __shared__ float xs[10][IN_DIMS];
    __shared__ float ws[10][EMB];
    int t = threadIdx.x;
    int i0 = (t >> 4) * 8;
    int e0 = (t & 15) * 4;
    float acc[8][4];
    #pragma unroll
    for (int a = 0; a < 8; a++)
        #pragma unroll
        for (int b = 0; b < 4; b++) acc[a][b] = 0.f;
    int rbase = blockIdx.x * 100;
    for (int c = 0; c < 10; c++) {
        for (int i = t; i < 10*IN_DIMS; i += 256) {
            int r = rbase + c*10 + i / IN_DIMS;
            xs[i / IN_DIMS][i % IN_DIMS] = x[(size_t)r*IN_DIMS + (i % IN_DIMS)];
        }
        for (int i = t; i < 10*EMB; i += 256) {
            int r = rbase + c*10 + i / EMB;
            ws[i / EMB][i % EMB] = W1[(size_t)r*EMB + (i % EMB)];
        }
        __syncthreads();
        #pragma unroll
        for (int rr = 0; rr < 10; rr++) {
            float wv[4];
            #pragma unroll
            for (int j = 0; j < 4; j++) wv[j] = ws[rr][e0 + j];
            #pragma unroll
            for (int ii = 0; ii < 8; ii++) {
                float xv = xs[rr][i0 + ii];
                #pragma unroll
                for (int j = 0; j < 4; j++) acc[ii][j] += xv * wv[j];
            }
        }
        __syncthreads();
    }
    #pragma unroll
    for (int ii = 0; ii < 8; ii++)
        #pragma unroll
        for (int j = 0; j < 4; j++)
            atomicAdd(&g_attr_part[(i0+ii)*EMB + e0 + j], acc[ii][j]);
}

__global__ __launch_bounds__(256) void k_attr2(const float* __restrict__ b1,
                                               const float* __restrict__ W2,
                                               const float* __restrict__ b2) {
    __shared__ float xa1[IN_DIMS*EMB];
    __shared__ float W2s[EMB*HID];
    int t = threadIdx.x;
    for (int i = t; i < IN_DIMS*EMB; i += 256)
        xa1[i] = fmaxf(g_attr_part[i] + b1[i % EMB], 0.f);
    for (int i = t; i < EMB*HID; i += 256) W2s[i] = W2[i];
    __syncthreads();
    int i0 = (t >> 4) * 8;
    int h0 = (t & 15) * 4;
    float acc[8][4];
    #pragma unroll
    for (int a = 0; a < 8; a++)
        #pragma unroll
        for (int b = 0; b < 4; b++) acc[a][b] = 0.f;
    for (int k = 0; k < EMB; k++) {
        float wv[4];
        #pragma unroll
        for (int j = 0; j < 4; j++) wv[j] = W2s[k*HID + h0 + j];
        #pragma unroll
        for (int ii = 0; ii < 8; ii++) {
            float xv = xa1[(i0+ii)*EMB + k];
            #pragma unroll
            for (int j = 0; j < 4; j++) acc[ii][j] += xv * wv[j];
        }
    }
    #pragma unroll
    for (int ii = 0; ii < 8; ii++)
        #pragma unroll
        for (int j = 0; j < 4; j++)
            g_xa2[(i0+ii)*HID + h0 + j] = acc[ii][j] + b2[h0 + j];
}

// x_ = embP @ xa2^T    [N,64]x[64,128] -> [N,128]
__global__ __launch_bounds__(256) void k_xout(float* __restrict__ out) {
    __shared__ float xa[IN_DIMS*(HID+1)];
    __shared__ float es[32*HID];
    int t = threadIdx.x;
    for (int i = t; i < IN_DIMS*HID; i += 256) {
        int r = i / HID, c = i % HID;
        xa[r*(HID+1) + c] = g_xa2[i];
    }
    int nb = blockIdx.x * 32;
    for (int i = t; i < 32*HID; i += 256) es[i] = g_embP[nb*HID + i];
    __syncthreads();
    int nl = t >> 3;
    int ib = (t & 7) * 16;
    const float* e = &es[nl*HID];
    int n = nb + nl;
    if (n >= N_NODES) return;
    for (int ii = 0; ii < 16; ii++) {
        int i = ib + ii;
        const float* w = &xa[i*(HID+1)];
        float acc = 0.f;
        #pragma unroll 8
        for (int k = 0; k < HID; k++) acc += e[k]*w[k];
        out[(size_t)n*IN_DIMS + i] = acc;
    }
}

// ---------------- tensor-core s_ GEMM (full grid, row-major stores only) ----
#define SPAD 24

__device__ __forceinline__ void mma16816(float c[4], uint32_t a0, uint32_t a1,
                                         uint32_t a2, uint32_t a3,
                                         uint32_t b0, uint32_t b1) {
    asm volatile(
        "mma.sync.aligned.m16n8k16.row.col.f32.bf16.bf16.f32 "
        "{%0,%1,%2,%3}, {%4,%5,%6,%7}, {%8,%9}, {%0,%1,%2,%3};"
        : "+f"(c[0]), "+f"(c[1]), "+f"(c[2]), "+f"(c[3])
        : "r"(a0), "r"(a1), "r"(a2), "r"(a3), "r"(b0), "r"(b1));
}

__global__ __launch_bounds__(256) void k_s_mma(float* __restrict__ sout) {
    __shared__ __align__(16) __nv_bfloat16 As[TILE][SPAD];
    __shared__ __align__(16) __nv_bfloat16 Bs[TILE][SPAD];

    int ti = blockIdx.x / NT;
    int tj = blockIdx.x % NT;

    int t = threadIdx.x;
    int warp = t >> 5, lane = t & 31;
    int wm = warp >> 1, wn = warp & 1;       // 4x2 warps: warp tile 32x64
    int g = lane >> 2, tq = lane & 3;

    int ldrow = t >> 1;
    int ldpart = (t & 1) * 8;

    const __nv_bfloat16* gA = &g_Abf[((size_t)ti*TILE + ldrow)*KSPLIT + ldpart];
    const __nv_bfloat16* gB = &g_Bbf[((size_t)tj*TILE + ldrow)*KSPLIT + ldpart];

    float c[2][8][4];
    #pragma unroll
    for (int mt = 0; mt < 2; mt++)
        #pragma unroll
        for (int nt = 0; nt < 8; nt++)
            #pragma unroll
            for (int r = 0; r < 4; r++) c[mt][nt][r] = 0.f;

    for (int ks = 0; ks < KSPLIT/16; ks++) {
        *(float4*)&As[ldrow][ldpart] = *(const float4*)(gA + ks*16);
        *(float4*)&Bs[ldrow][ldpart] = *(const float4*)(gB + ks*16);
        __syncthreads();

        uint32_t a[2][4];
        #pragma unroll
        for (int mt = 0; mt < 2; mt++) {
            int ar = wm*32 + mt*16 + g;
            a[mt][0] = *(const uint32_t*)&As[ar][tq*2];
            a[mt][1] = *(const uint32_t*)&As[ar+8][tq*2];
            a[mt][2] = *(const uint32_t*)&As[ar][tq*2+8];
            a[mt][3] = *(const uint32_t*)&As[ar+8][tq*2+8];
        }
        #pragma unroll
        for (int nt = 0; nt < 8; nt++) {
            int br = wn*64 + nt*8 + g;
            uint32_t b0 = *(const uint32_t*)&Bs[br][tq*2];
            uint32_t b1 = *(const uint32_t*)&Bs[br][tq*2+8];
            mma16816(c[0][nt], a[0][0], a[0][1], a[0][2], a[0][3], b0, b1);
            mma16816(c[1][nt], a[1][0], a[1][1], a[1][2], a[1][3], b0, b1);
        }
        __syncthreads();
    }

    #pragma unroll
    for (int mt = 0; mt < 2; mt++)
        #pragma unroll
        for (int nt = 0; nt < 8; nt++)
            #pragma unroll
            for (int r = 0; r < 4; r++)
                c[mt][nt][r] = 1.f / (1.f + __expf(-c[mt][nt][r]));

    #pragma unroll
    for (int mt = 0; mt < 2; mt++) {
        #pragma unroll
        for (int rr = 0; rr < 2; rr++) {
            int gr = ti*TILE + wm*32 + mt*16 + g + rr*8;
            if (gr >= N_NODES) continue;
            size_t obase = (size_t)gr * N_NODES;
            #pragma unroll
            for (int nt = 0; nt < 8; nt++) {
                int gc = tj*TILE + wn*64 + nt*8 + tq*2;
                if (gc < N_NODES)
                    *(float2*)&sout[obase + gc] =
                        make_float2(c[mt][nt][rr*2], c[mt][nt][rr*2 + 1]);
            }
        }
    }
}

// ---------------- launch ----------------
extern "C" void kernel_launch(void* const* d_in, const int* in_sizes, int n_in,
                              void* d_out, int out_size) {
    const float* x       = (const float*)d_in[0];
    const int*   ei      = (const int*)d_in[1];
    const float* W_stru  = (const float*)d_in[3];
    const float* b_stru  = (const float*)d_in[4];
    const float* W_gat   = (const float*)d_in[5];
    const float* att_src = (const float*)d_in[6];
    const float* att_dst = (const float*)d_in[7];
    const float* b_gat   = (const float*)d_in[8];
    const float* W_attr1 = (const float*)d_in[9];
    const float* b_attr1 = (const float*)d_in[10];
    const float* W_attr2 = (const float*)d_in[11];
    const float* b_attr2 = (const float*)d_in[12];

    int E = in_sizes[1] / 2;
    int EN = E + N_NODES;

    float* out   = (float*)d_out;
    float* x_out = out;
    float* s_out = out + (size_t)N_NODES * IN_DIMS;

    k_zero  <<<148, 256>>>();
    k_stru  <<<(N_NODES + 15) / 16, 256>>>(x, W_stru, b_stru);
    k_gatlin<<<(N_NODES + 15) / 16, 256>>>(W_gat);
    k_att   <<<(N_NODES * 32 + 255) / 256, 256>>>(att_src, att_dst);
    k_emax  <<<(EN + 255) / 256, 256>>>(ei, E);
    k_scan  <<<1, 1024>>>();
    k_eexp  <<<(EN + 255) / 256, 256>>>(ei, E);
    k_aggr  <<<(N_NODES * 32 + 255) / 256, 256>>>(E);
    k_femb  <<<(NPAD * HID + 255) / 256, 256>>>(b_gat);
    k_attr1 <<<100, 256>>>(x, W_attr1);
    k_attr2 <<<1, 256>>>(b_attr1, W_attr2, b_attr2);
    k_xout  <<<(N_NODES + 31) / 32, 256>>>(x_out);
    k_s_mma <<<NT * NT, 256>>>(s_out);
}

// round 5
// speedup vs baseline: 1.2232x; 1.2232x over previous
#include <cuda_runtime.h>
#include <cuda_bf16.h>
#include <math.h>
#include <stdint.h>

#define N_NODES 10000
#define IN_DIMS 128
#define EMB 64
#define HID 64
#define NEG_SLOPE 0.2f
#define TILE 128
#define NT 79                 // ceil(N/128)
#define NPAD (NT*TILE)        // 10112
#define MAXEDGE 400000
#define KS 128                // [hi|lo] packed split matrix

// ---------------- scratch (no allocations allowed) ----------------
__device__ float    g_h[N_NODES*EMB];
__device__ float    g_hp[N_NODES*HID];
__device__ float    g_asrc[N_NODES];
__device__ float    g_adst[N_NODES];
__device__ float    g_w[MAXEDGE + N_NODES];
__device__ float    g_emb_acc[N_NODES*HID];
__device__ float    g_embP[NPAD*HID];
__device__ float    g_attr_part[IN_DIMS*EMB];
__device__ float    g_xa2[IN_DIMS*HID];
__device__ __align__(16) __nv_bfloat16 g_Ebf[NPAD*KS];   // [hi(64) | lo(64)]
// CSR scratch
__device__ int g_deg[N_NODES];
__device__ int g_cur[N_NODES];
__device__ int g_off[N_NODES + 1];
__device__ int2 g_epack[MAXEDGE + N_NODES];   // (src, edge-id)

// ---------------- small kernels ----------------
__global__ void k_zero() {
    int i = blockIdx.x * blockDim.x + threadIdx.x;
    int stride = gridDim.x * blockDim.x;
    for (int j = i; j < N_NODES; j += stride) { g_deg[j] = 0; g_cur[j] = 0; }
    for (int j = i; j < IN_DIMS*EMB; j += stride) g_attr_part[j] = 0.f;
}

__global__ __launch_bounds__(256) void k_stru(const float* __restrict__ x,
                                              const float* __restrict__ W,
                                              const float* __restrict__ b) {
    __shared__ float Ws[IN_DIMS*EMB];
    __shared__ float xs[16*IN_DIMS];
    int t = threadIdx.x;
    for (int i = t; i < IN_DIMS*EMB; i += 256) Ws[i] = W[i];
    int nbase = blockIdx.x * 16;
    for (int i = t; i < 16*IN_DIMS; i += 256) {
        int n = nbase + i / IN_DIMS;
        xs[i] = (n < N_NODES) ? x[(size_t)n*IN_DIMS + (i % IN_DIMS)] : 0.f;
    }
    __syncthreads();
    int nl = t >> 4;
    int e0 = (t & 15) * 4;
    float a0=0.f, a1=0.f, a2=0.f, a3=0.f;
    #pragma unroll 4
    for (int k = 0; k < IN_DIMS; k++) {
        float xv = xs[nl*IN_DIMS + k];
        const float* w = &Ws[k*EMB + e0];
        a0 += xv*w[0]; a1 += xv*w[1]; a2 += xv*w[2]; a3 += xv*w[3];
    }
    int n = nbase + nl;
    if (n < N_NODES) {
        float* o = &g_h[n*EMB + e0];
        o[0] = fmaxf(a0 + b[e0+0], 0.f);
        o[1] = fmaxf(a1 + b[e0+1], 0.f);
        o[2] = fmaxf(a2 + b[e0+2], 0.f);
        o[3] = fmaxf(a3 + b[e0+3], 0.f);
    }
}

__global__ __launch_bounds__(256) void k_gatlin(const float* __restrict__ W) {
    __shared__ float Ws[EMB*HID];
    __shared__ float hs[16*EMB];
    int t = threadIdx.x;
    for (int i = t; i < EMB*HID; i += 256) Ws[i] = W[i];
    int nbase = blockIdx.x * 16;
    for (int i = t; i < 16*EMB; i += 256) {
        int n = nbase + i / EMB;
        hs[i] = (n < N_NODES) ? g_h[n*EMB + (i % EMB)] : 0.f;
    }
    __syncthreads();
    int nl = t >> 4;
    int e0 = (t & 15) * 4;
    float a0=0.f, a1=0.f, a2=0.f, a3=0.f;
    #pragma unroll 8
    for (int k = 0; k < EMB; k++) {
        float xv = hs[nl*EMB + k];
        const float* w = &Ws[k*HID + e0];
        a0 += xv*w[0]; a1 += xv*w[1]; a2 += xv*w[2]; a3 += xv*w[3];
    }
    int n = nbase + nl;
    if (n < N_NODES) {
        float* o = &g_hp[n*HID + e0];
        o[0]=a0; o[1]=a1; o[2]=a2; o[3]=a3;
    }
}

__global__ void k_att(const float* __restrict__ att_s, const float* __restrict__ att_d) {
    int warp = (blockIdx.x * blockDim.x + threadIdx.x) >> 5;
    int lane = threadIdx.x & 31;
    if (warp >= N_NODES) return;
    float h0 = g_hp[warp*HID + lane];
    float h1 = g_hp[warp*HID + 32 + lane];
    float s = h0*att_s[lane] + h1*att_s[32+lane];
    float d = h0*att_d[lane] + h1*att_d[32+lane];
    #pragma unroll
    for (int o = 16; o; o >>= 1) {
        s += __shfl_xor_sync(0xffffffffu, s, o);
        d += __shfl_xor_sync(0xffffffffu, d, o);
    }
    if (lane == 0) { g_asrc[warp] = s; g_adst[warp] = d; }
}

// per edge: w = exp(leaky_relu(a_src+a_dst)) (no max shift needed), degree count
__global__ void k_edge1(const int* __restrict__ ei, int E) {
    int i = blockIdx.x * blockDim.x + threadIdx.x;
    if (i >= E + N_NODES) return;
    int s, d;
    if (i < E) { s = ei[i]; d = ei[E + i]; } else { s = d = i - E; }
    float e = g_asrc[s] + g_adst[d];
    e = (e > 0.f) ? e : NEG_SLOPE * e;
    g_w[i] = __expf(e);
    atomicAdd(&g_deg[d], 1);
}

__global__ __launch_bounds__(1024) void k_scan() {
    __shared__ int tmp[1024];
    __shared__ int carry;
    int t = threadIdx.x;
    if (t == 0) carry = 0;
    __syncthreads();
    for (int base = 0; base < N_NODES; base += 1024) {
        int i = base + t;
        int v = (i < N_NODES) ? g_deg[i] : 0;
        tmp[t] = v;
        __syncthreads();
        for (int off = 1; off < 1024; off <<= 1) {
            int add = (t >= off) ? tmp[t - off] : 0;
            __syncthreads();
            tmp[t] += add;
            __syncthreads();
        }
        if (i < N_NODES) g_off[i + 1] = carry + tmp[t];
        __syncthreads();
        if (t == 1023) carry += tmp[1023];
        __syncthreads();
    }
    if (t == 0) g_off[0] = 0;
}

__global__ void k_edge2(const int* __restrict__ ei, int E) {
    int i = blockIdx.x * blockDim.x + threadIdx.x;
    if (i >= E + N_NODES) return;
    int s, d;
    if (i < E) { s = ei[i]; d = ei[E + i]; } else { s = d = i - E; }
    int pos = g_off[d] + atomicAdd(&g_cur[d], 1);
    g_epack[pos] = make_int2(s, i);
}

// warp per dst: register accumulation + local denominator
__global__ void k_aggr(int E) {
    int d = (blockIdx.x * blockDim.x + threadIdx.x) >> 5;
    int lane = threadIdx.x & 31;
    if (d >= N_NODES) return;
    int beg = g_off[d], end = g_off[d + 1];
    float wsum = 0.f, a0 = 0.f, a1 = 0.f;
    for (int p = beg; p < end; p++) {
        int2 pk = g_epack[p];
        float w = g_w[pk.y];
        wsum += w;
        a0 += g_hp[pk.x*HID + lane]      * w;
        a1 += g_hp[pk.x*HID + 32 + lane] * w;
    }
    float inv = 1.f / wsum;
    g_emb_acc[d*HID + lane]      = a0 * inv;
    g_emb_acc[d*HID + 32 + lane] = a1 * inv;
}

// embP = emb_acc + b_gat, plus bf16 [hi|lo] split for the MMA GEMM
__global__ void k_femb(const float* __restrict__ bg) {
    int i = blockIdx.x * blockDim.x + threadIdx.x;
    if (i >= NPAD*HID) return;
    int n = i >> 6, j = i & 63;
    float v = (n < N_NODES) ? (g_emb_acc[i] + bg[j]) : 0.f;
    g_embP[i] = v;
    __nv_bfloat16 hi = __float2bfloat16(v);
    __nv_bfloat16 lo = __float2bfloat16(v - __bfloat162float(hi));
    size_t base = (size_t)n * KS + j;
    g_Ebf[base]      = hi;
    g_Ebf[base + 64] = lo;
}

__global__ __launch_bounds__(256) void k_attr1(const float* __restrict__ x,
                                               const float* __restrict__ W1) {
    __shared__ float xs[10][IN_DIMS];
    __shared__ float ws[10][EMB];
    int t = threadIdx.x;
    int i0 = (t >> 4) * 8;
    int e0 = (t & 15) * 4;
    float acc[8][4];
    #pragma unroll
    for (int a = 0; a < 8; a++)
        #pragma unroll
        for (int b = 0; b < 4; b++) acc[a][b] = 0.f;
    int rbase = blockIdx.x * 100;
    for (int c = 0; c < 10; c++) {
        for (int i = t; i < 10*IN_DIMS; i += 256) {
            int r = rbase + c*10 + i / IN_DIMS;
            xs[i / IN_DIMS][i % IN_DIMS] = x[(size_t)r*IN_DIMS + (i % IN_DIMS)];
        }
        for (int i = t; i < 10*EMB; i += 256) {
            int r = rbase + c*10 + i / EMB;
            ws[i / EMB][i % EMB] = W1[(size_t)r*EMB + (i % EMB)];
        }
        __syncthreads();
        #pragma unroll
        for (int rr = 0; rr < 10; rr++) {
            float wv[4];
            #pragma unroll
            for (int j = 0; j < 4; j++) wv[j] = ws[rr][e0 + j];
            #pragma unroll
            for (int ii = 0; ii < 8; ii++) {
                float xv = xs[rr][i0 + ii];
                #pragma unroll
                for (int j = 0; j < 4; j++) acc[ii][j] += xv * wv[j];
            }
        }
        __syncthreads();
    }
    #pragma unroll
    for (int ii = 0; ii < 8; ii++)
        #pragma unroll
        for (int j = 0; j < 4; j++)
            atomicAdd(&g_attr_part[(i0+ii)*EMB + e0 + j], acc[ii][j]);
}

__global__ __launch_bounds__(256) void k_attr2(const float* __restrict__ b1,
                                               const float* __restrict__ W2,
                                               const float* __restrict__ b2) {
    __shared__ float xa1[IN_DIMS*EMB];
    __shared__ float W2s[EMB*HID];
    int t = threadIdx.x;
    for (int i = t; i < IN_DIMS*EMB; i += 256)
        xa1[i] = fmaxf(g_attr_part[i] + b1[i % EMB], 0.f);
    for (int i = t; i < EMB*HID; i += 256) W2s[i] = W2[i];
    __syncthreads();
    int i0 = (t >> 4) * 8;
    int h0 = (t & 15) * 4;
    float acc[8][4];
    #pragma unroll
    for (int a = 0; a < 8; a++)
        #pragma unroll
        for (int b = 0; b < 4; b++) acc[a][b] = 0.f;
    for (int k = 0; k < EMB; k++) {
        float wv[4];
        #pragma unroll
        for (int j = 0; j < 4; j++) wv[j] = W2s[k*HID + h0 + j];
        #pragma unroll
        for (int ii = 0; ii < 8; ii++) {
            float xv = xa1[(i0+ii)*EMB + k];
            #pragma unroll
            for (int j = 0; j < 4; j++) acc[ii][j] += xv * wv[j];
        }
    }
    #pragma unroll
    for (int ii = 0; ii < 8; ii++)
        #pragma unroll
        for (int j = 0; j < 4; j++)
            g_xa2[(i0+ii)*HID + h0 + j] = acc[ii][j] + b2[h0 + j];
}

__global__ __launch_bounds__(256) void k_xout(float* __restrict__ out) {
    __shared__ float xa[IN_DIMS*(HID+1)];
    __shared__ float es[32*HID];
    int t = threadIdx.x;
    for (int i = t; i < IN_DIMS*HID; i += 256) {
        int r = i / HID, c = i % HID;
        xa[r*(HID+1) + c] = g_xa2[i];
    }
    int nb = blockIdx.x * 32;
    for (int i = t; i < 32*HID; i += 256) es[i] = g_embP[nb*HID + i];
    __syncthreads();
    int nl = t >> 3;
    int ib = (t & 7) * 16;
    const float* e = &es[nl*HID];
    int n = nb + nl;
    if (n >= N_NODES) return;
    for (int ii = 0; ii < 16; ii++) {
        int i = ib + ii;
        const float* w = &xa[i*(HID+1)];
        float acc = 0.f;
        #pragma unroll 8
        for (int k = 0; k < HID; k++) acc += e[k]*w[k];
        out[(size_t)n*IN_DIMS + i] = acc;
    }
}

// ================= mma.sync s_ GEMM, symmetric, ldmatrix, 1 sync =============
// smem: A and B tiles 128 x 128 bf16, row stride 272B (conflict-free ldmatrix)
#define ROWB 272
#define BOFF 34816            // 128*272
#define SMEM_S (2*34816)      // 69632 B dynamic

__device__ __forceinline__ uint32_t smem_u32(const void* p) {
    uint32_t a;
    asm("{ .reg .u64 t; cvta.to.shared.u64 t, %1; cvt.u32.u64 %0, t; }" : "=r"(a) : "l"(p));
    return a;
}
__device__ __forceinline__ void ldsm4(uint32_t addr, uint32_t& r0, uint32_t& r1,
                                      uint32_t& r2, uint32_t& r3) {
    asm volatile("ldmatrix.sync.aligned.m8n8.x4.shared.b16 {%0,%1,%2,%3}, [%4];"
                 : "=r"(r0), "=r"(r1), "=r"(r2), "=r"(r3) : "r"(addr));
}
__device__ __forceinline__ void mma16816(float c[4], uint32_t a0, uint32_t a1,
                                         uint32_t a2, uint32_t a3,
                                         uint32_t b0, uint32_t b1) {
    asm volatile(
        "mma.sync.aligned.m16n8k16.row.col.f32.bf16.bf16.f32 "
        "{%0,%1,%2,%3}, {%4,%5,%6,%7}, {%8,%9}, {%0,%1,%2,%3};"
        : "+f"(c[0]), "+f"(c[1]), "+f"(c[2]), "+f"(c[3])
        : "r"(a0), "r"(a1), "r"(a2), "r"(a3), "r"(b0), "r"(b1));
}

extern __shared__ char smem_s[];

__global__ __launch_bounds__(256) void k_s_mma(float* __restrict__ sout) {
    // triangle decode: tj >= ti
    int b = blockIdx.x;
    int ti = 0;
    {
        int rem = b, rowlen = NT;
        while (rem >= rowlen) { rem -= rowlen; ti++; rowlen--; }
        b = rem;
    }
    int tj = ti + b;

    int t = threadIdx.x;
    int warp = t >> 5, lane = t & 31;
    int wm = warp >> 1, wn = warp & 1;      // 4x2 warps -> 32x64 warp tile
    int g = lane >> 2, tq = lane & 3;
    int q = lane >> 3, r8 = lane & 7;       // ldmatrix lane decomposition

    // ---- cooperative load: both tiles (128 x 128 bf16 each) ----
    const __nv_bfloat16* gA = &g_Ebf[(size_t)ti * TILE * KS];
    const __nv_bfloat16* gB = &g_Ebf[(size_t)tj * TILE * KS];
    #pragma unroll
    for (int i = 0; i < 8; i++) {
        int v = i * 256 + t;                // 0..2047 float4 slots per matrix
        int row = v >> 4;
        int c16 = v & 15;
        *(float4*)(smem_s + row*ROWB + c16*16)        = *(const float4*)(gA + row*KS + c16*8);
        *(float4*)(smem_s + BOFF + row*ROWB + c16*16) = *(const float4*)(gB + row*KS + c16*8);
    }
    __syncthreads();

    uint32_t sA = smem_u32(smem_s);
    uint32_t sB = sA + BOFF;

    // per-lane ldmatrix base addresses (k-offset added per step)
    uint32_t aAddr[2], bAddr[4];
    #pragma unroll
    for (int mt = 0; mt < 2; mt++)
        aAddr[mt] = sA + (uint32_t)(wm*32 + mt*16 + r8 + (q & 1)*8)*ROWB + (uint32_t)((q >> 1)*8)*2;
    #pragma unroll
    for (int n2 = 0; n2 < 4; n2++)
        bAddr[n2] = sB + (uint32_t)(wn*64 + n2*16 + r8 + (q >> 1)*8)*ROWB + (uint32_t)((q & 1)*8)*2;

    float c[2][8][4];
    #pragma unroll
    for (int mt = 0; mt < 2; mt++)
        #pragma unroll
        for (int nt = 0; nt < 8; nt++)
            #pragma unroll
            for (int rr = 0; rr < 4; rr++) c[mt][nt][rr] = 0.f;

    // 3 passes: (hiA,hiB), (loA,hiB), (hiA,loB); 4 k-steps of 16 each
    #pragma unroll
    for (int s = 0; s < 12; s++) {
        int pass = s >> 2;
        int kk = (s & 3) * 16;
        uint32_t ka = (uint32_t)(((pass == 1) ? 64 : 0) + kk) * 2;   // bytes
        uint32_t kb = (uint32_t)(((pass == 2) ? 64 : 0) + kk) * 2;

        uint32_t a[2][4];
        #pragma unroll
        for (int mt = 0; mt < 2; mt++)
            ldsm4(aAddr[mt] + ka, a[mt][0], a[mt][1], a[mt][2], a[mt][3]);

        #pragma unroll
        for (int n2 = 0; n2 < 4; n2++) {
            uint32_t b0, b1, b2, b3;
            ldsm4(bAddr[n2] + kb, b0, b1, b2, b3);
            int nt = n2 * 2;
            mma16816(c[0][nt],   a[0][0], a[0][1], a[0][2], a[0][3], b0, b1);
            mma16816(c[1][nt],   a[1][0], a[1][1], a[1][2], a[1][3], b0, b1);
            mma16816(c[0][nt+1], a[0][0], a[0][1], a[0][2], a[0][3], b2, b3);
            mma16816(c[1][nt+1], a[1][0], a[1][1], a[1][2], a[1][3], b2, b3);
        }
    }

    // sigmoid
    #pragma unroll
    for (int mt = 0; mt < 2; mt++)
        #pragma unroll
        for (int nt = 0; nt < 8; nt++)
            #pragma unroll
            for (int rr = 0; rr < 4; rr++)
                c[mt][nt][rr] = 1.f / (1.f + __expf(-c[mt][nt][rr]));

    bool diag = (ti == tj);
    #pragma unroll
    for (int mt = 0; mt < 2; mt++) {
        #pragma unroll
        for (int rr = 0; rr < 2; rr++) {
            int gr = ti*TILE + wm*32 + mt*16 + g + rr*8;
            bool rok = gr < N_NODES;
            size_t obase = (size_t)gr * N_NODES;
            #pragma unroll
            for (int nt = 0; nt < 8; nt++) {
                int gc = tj*TILE + wn*64 + nt*8 + tq*2;
                float v0 = c[mt][nt][rr*2 + 0];
                float v1 = c[mt][nt][rr*2 + 1];
                if (rok && gc < N_NODES)
                    *(float2*)&sout[obase + gc] = make_float2(v0, v1);
                if (!diag && rok && gc < N_NODES) {
                    sout[(size_t)gc * N_NODES + gr]     = v0;
                    sout[(size_t)(gc+1) * N_NODES + gr] = v1;
                }
            }
        }
    }
}

// ---------------- launch ----------------
extern "C" void kernel_launch(void* const* d_in, const int* in_sizes, int n_in,
                              void* d_out, int out_size) {
    const float* x       = (const float*)d_in[0];
    const int*   ei      = (const int*)d_in[1];
    const float* W_stru  = (const float*)d_in[3];
    const float* b_stru  = (const float*)d_in[4];
    const float* W_gat   = (const float*)d_in[5];
    const float* att_src = (const float*)d_in[6];
    const float* att_dst = (const float*)d_in[7];
    const float* b_gat   = (const float*)d_in[8];
    const float* W_attr1 = (const float*)d_in[9];
    const float* b_attr1 = (const float*)d_in[10];
    const float* W_attr2 = (const float*)d_in[11];
    const float* b_attr2 = (const float*)d_in[12];

    int E = in_sizes[1] / 2;
    int EN = E + N_NODES;

    float* out   = (float*)d_out;
    float* x_out = out;
    float* s_out = out + (size_t)N_NODES * IN_DIMS;

    cudaFuncSetAttribute(k_s_mma, cudaFuncAttributeMaxDynamicSharedMemorySize, SMEM_S);

    k_zero  <<<148, 256>>>();
    k_stru  <<<(N_NODES + 15) / 16, 256>>>(x, W_stru, b_stru);
    k_gatlin<<<(N_NODES + 15) / 16, 256>>>(W_gat);
    k_att   <<<(N_NODES * 32 + 255) / 256, 256>>>(att_src, att_dst);
    k_edge1 <<<(EN + 255) / 256, 256>>>(ei, E);
    k_scan  <<<1, 1024>>>();
    k_edge2 <<<(EN + 255) / 256, 256>>>(ei, E);
    k_aggr  <<<(N_NODES * 32 + 255) / 256, 256>>>(E);
    k_femb  <<<(NPAD * HID + 255) / 256, 256>>>(b_gat);
    k_attr1 <<<100, 256>>>(x, W_attr1);
    k_attr2 <<<1, 256>>>(b_attr1, W_attr2, b_attr2);
    k_xout  <<<(N_NODES + 31) / 32, 256>>>(x_out);
    k_s_mma <<<NT * (NT + 1) / 2, 256, SMEM_S>>>(s_out);
}

// round 6
// speedup vs baseline: 1.2951x; 1.0588x over previous
#include <cuda_runtime.h>
#include <cuda_bf16.h>
#include <math.h>
#include <stdint.h>

#define N_NODES 10000
#define IN_DIMS 128
#define EMB 64
#define HID 64
#define NEG_SLOPE 0.2f
#define TILE 128
#define NT 79                 // ceil(N/128)
#define NPAD (NT*TILE)        // 10112
#define MAXEDGE 400000
#define KS 128                // [hi|lo] packed split matrix

// ---------------- scratch (no allocations allowed) ----------------
__device__ float    g_hp[N_NODES*HID];
__device__ float    g_asrc[N_NODES];
__device__ float    g_adst[N_NODES];
__device__ float    g_embP[N_NODES*HID];
__device__ float    g_attr_part[IN_DIMS*EMB];
__device__ float    g_xa2[IN_DIMS*HID];
// zero-initialized at load; pad rows (>=N_NODES) are NEVER written -> stay 0
__device__ __align__(16) __nv_bfloat16 g_Ebf[NPAD*KS];   // [hi(64) | lo(64)]
// CSR scratch
__device__ int g_deg[N_NODES];
__device__ int g_cur[N_NODES];
__device__ int g_off[N_NODES + 1];
__device__ int2 g_epack[MAXEDGE + N_NODES];   // (src, float-bits of w)

// ---------------- kernels ----------------
__global__ void k_zero() {
    int i = blockIdx.x * blockDim.x + threadIdx.x;
    int stride = gridDim.x * blockDim.x;
    for (int j = i; j < N_NODES; j += stride) { g_deg[j] = 0; g_cur[j] = 0; }
    for (int j = i; j < IN_DIMS*EMB; j += stride) g_attr_part[j] = 0.f;
}

// ===== fused encoder: hp = relu(x@W1+b1)@W2 ; a_src/a_dst dot products =====
// 16 nodes per block, 256 threads. Dynamic smem 60KB.
extern __shared__ float s_enc[];
__global__ __launch_bounds__(256) void k_enc(const float* __restrict__ x,
                                             const float* __restrict__ W1,
                                             const float* __restrict__ b1,
                                             const float* __restrict__ W2,
                                             const float* __restrict__ att_s,
                                             const float* __restrict__ att_d) {
    float* Ws1 = s_enc;            // 8192 floats
    float* Ws2 = s_enc + 8192;     // 4096
    float* xs  = s_enc + 12288;    // 2048
    float* hs  = s_enc + 14336;    // 1024
    __shared__ float As[HID], Ad[HID], Bs1[EMB];

    int t = threadIdx.x;
    int nbase = blockIdx.x * 16;

    #pragma unroll
    for (int i = 0; i < 8; i++)
        ((float4*)Ws1)[t + i*256] = ((const float4*)W1)[t + i*256];
    #pragma unroll
    for (int i = 0; i < 4; i++)
        ((float4*)Ws2)[t + i*256] = ((const float4*)W2)[t + i*256];
    #pragma unroll
    for (int i = 0; i < 2; i++)
        ((float4*)xs)[t + i*256] =
            ((const float4*)x)[(size_t)nbase*32 + t + i*256];
    if (t < HID) { As[t] = att_s[t]; Ad[t] = att_d[t]; }
    else if (t < 128) { Bs1[t - HID] = b1[t - HID]; }
    __syncthreads();

    int nl = t >> 4;
    int e0 = (t & 15) * 4;

    // phase 1: h = relu(x@W1 + b1)
    {
        float a0=0.f, a1=0.f, a2=0.f, a3=0.f;
        const float* xr = &xs[nl*IN_DIMS];
        #pragma unroll 4
        for (int k = 0; k < IN_DIMS; k++) {
            float xv = xr[k];
            float4 w = *(const float4*)&Ws1[k*EMB + e0];
            a0 += xv*w.x; a1 += xv*w.y; a2 += xv*w.z; a3 += xv*w.w;
        }
        float4 h4 = make_float4(fmaxf(a0 + Bs1[e0+0], 0.f),
                                fmaxf(a1 + Bs1[e0+1], 0.f),
                                fmaxf(a2 + Bs1[e0+2], 0.f),
                                fmaxf(a3 + Bs1[e0+3], 0.f));
        *(float4*)&hs[nl*EMB + e0] = h4;
    }
    __syncthreads();

    // phase 2: hp = h@W2 (no bias), attention partials
    {
        float a0=0.f, a1=0.f, a2=0.f, a3=0.f;
        const float* hr = &hs[nl*EMB];
        #pragma unroll 8
        for (int k = 0; k < EMB; k++) {
            float hv = hr[k];
            float4 w = *(const float4*)&Ws2[k*HID + e0];
            a0 += hv*w.x; a1 += hv*w.y; a2 += hv*w.z; a3 += hv*w.w;
        }
        int n = nbase + nl;
        *(float4*)&g_hp[(size_t)n*HID + e0] = make_float4(a0, a1, a2, a3);
        float ps = a0*As[e0] + a1*As[e0+1] + a2*As[e0+2] + a3*As[e0+3];
        float pd = a0*Ad[e0] + a1*Ad[e0+1] + a2*Ad[e0+2] + a3*Ad[e0+3];
        #pragma unroll
        for (int o = 8; o; o >>= 1) {
            ps += __shfl_down_sync(0xffffffffu, ps, o, 16);
            pd += __shfl_down_sync(0xffffffffu, pd, o, 16);
        }
        if ((t & 15) == 0) { g_asrc[n] = ps; g_adst[n] = pd; }
    }
}

// degree count only
__global__ void k_edge1(const int* __restrict__ ei, int E) {
    int i = blockIdx.x * blockDim.x + threadIdx.x;
    if (i >= E + N_NODES) return;
    int d = (i < E) ? ei[E + i] : (i - E);
    atomicAdd(&g_deg[d], 1);
}

// 3-barrier block scan: 1024 threads x 10 elems
__global__ __launch_bounds__(1024) void k_scan2() {
    __shared__ int wsum[32];
    int t = threadIdx.x, lane = t & 31, wid = t >> 5;
    int base = t * 10;
    int v[10];
    int tot = 0;
    #pragma unroll
    for (int j = 0; j < 10; j++) {
        int idx = base + j;
        v[j] = (idx < N_NODES) ? g_deg[idx] : 0;
        tot += v[j];
    }
    int s = tot;
    #pragma unroll
    for (int o = 1; o < 32; o <<= 1) {
        int nv = __shfl_up_sync(0xffffffffu, s, o);
        if (lane >= o) s += nv;
    }
    if (lane == 31) wsum[wid] = s;
    __syncthreads();
    if (wid == 0) {
        int ws = wsum[lane];
        #pragma unroll
        for (int o = 1; o < 32; o <<= 1) {
            int nv = __shfl_up_sync(0xffffffffu, ws, o);
            if (lane >= o) ws += nv;
        }
        wsum[lane] = ws;
    }
    __syncthreads();
    int wex = wid ? wsum[wid - 1] : 0;
    int run = wex + s - tot;      // exclusive prefix for this thread
    #pragma unroll
    for (int j = 0; j < 10; j++) {
        int idx = base + j;
        if (idx < N_NODES) {
            g_off[idx] = run;
            run += v[j];
            if (idx == N_NODES - 1) g_off[N_NODES] = run;
        }
    }
}

// w = exp(leaky_relu(a_src+a_dst)); scatter (src, w) into CSR slot
__global__ void k_edge2(const int* __restrict__ ei, int E) {
    int i = blockIdx.x * blockDim.x + threadIdx.x;
    if (i >= E + N_NODES) return;
    int s, d;
    if (i < E) { s = ei[i]; d = ei[E + i]; } else { s = d = i - E; }
    float e = g_asrc[s] + g_adst[d];
    e = (e > 0.f) ? e : NEG_SLOPE * e;
    float w = __expf(e);
    int pos = g_off[d] + atomicAdd(&g_cur[d], 1);
    g_epack[pos] = make_int2(s, __float_as_int(w));
}

// warp per dst: softmax-weighted aggregation + bias + bf16 split (fused femb)
__global__ void k_aggr(const float* __restrict__ bg) {
    int d = (blockIdx.x * blockDim.x + threadIdx.x) >> 5;
    int lane = threadIdx.x & 31;
    if (d >= N_NODES) return;
    int beg = g_off[d], end = g_off[d + 1];
    float wsum = 0.f, a0 = 0.f, a1 = 0.f;
    for (int p = beg; p < end; p++) {
        int2 pk = g_epack[p];
        float w = __int_as_float(pk.y);
        wsum += w;
        a0 += g_hp[(size_t)pk.x*HID + lane]      * w;
        a1 += g_hp[(size_t)pk.x*HID + 32 + lane] * w;
    }
    float inv = 1.f / wsum;
    float v0 = a0 * inv + bg[lane];
    float v1 = a1 * inv + bg[lane + 32];
    g_embP[(size_t)d*HID + lane]      = v0;
    g_embP[(size_t)d*HID + 32 + lane] = v1;
    __nv_bfloat16 h0 = __float2bfloat16(v0);
    __nv_bfloat16 l0 = __float2bfloat16(v0 - __bfloat162float(h0));
    __nv_bfloat16 h1 = __float2bfloat16(v1);
    __nv_bfloat16 l1 = __float2bfloat16(v1 - __bfloat162float(h1));
    size_t eb = (size_t)d * KS;
    g_Ebf[eb + lane]      = h0;
    g_Ebf[eb + 64 + lane] = l0;
    g_Ebf[eb + 32 + lane] = h1;
    g_Ebf[eb + 96 + lane] = l1;
}

__global__ __launch_bounds__(256) void k_attr1(const float* __restrict__ x,
                                               const float* __restrict__ W1) {
    __shared__ float xs[10][IN_DIMS];
    __shared__ float ws[10][EMB];
    int t = threadIdx.x;
    int i0 = (t >> 4) * 8;
    int e0 = (t & 15) * 4;
    float acc[8][4];
    #pragma unroll
    for (int a = 0; a < 8; a++)
        #pragma unroll
        for (int b = 0; b < 4; b++) acc[a][b] = 0.f;
    int rbase = blockIdx.x * 100;
    for (int c = 0; c < 10; c++) {
        for (int i = t; i < 10*IN_DIMS; i += 256) {
            int r = rbase + c*10 + i / IN_DIMS;
            xs[i / IN_DIMS][i % IN_DIMS] = x[(size_t)r*IN_DIMS + (i % IN_DIMS)];
        }
        for (int i = t; i < 10*EMB; i += 256) {
            int r = rbase + c*10 + i / EMB;
            ws[i / EMB][i % EMB] = W1[(size_t)r*EMB + (i % EMB)];
        }
        __syncthreads();
        #pragma unroll
        for (int rr = 0; rr < 10; rr++) {
            float wv[4];
            #pragma unroll
            for (int j = 0; j < 4; j++) wv[j] = ws[rr][e0 + j];
            #pragma unroll
            for (int ii = 0; ii < 8; ii++) {
                float xv = xs[rr][i0 + ii];
                #pragma unroll
                for (int j = 0; j < 4; j++) acc[ii][j] += xv * wv[j];
            }
        }
        __syncthreads();
    }
    #pragma unroll
    for (int ii = 0; ii < 8; ii++)
        #pragma unroll
        for (int j = 0; j < 4; j++)
            atomicAdd(&g_attr_part[(i0+ii)*EMB + e0 + j], acc[ii][j]);
}

__global__ __launch_bounds__(256) void k_attr2(const float* __restrict__ b1,
                                               const float* __restrict__ W2,
                                               const float* __restrict__ b2) {
    __shared__ float xa1[IN_DIMS*EMB];
    __shared__ float W2s[EMB*HID];
    int t = threadIdx.x;
    for (int i = t; i < IN_DIMS*EMB; i += 256)
        xa1[i] = fmaxf(g_attr_part[i] + b1[i % EMB], 0.f);
    for (int i = t; i < EMB*HID; i += 256) W2s[i] = W2[i];
    __syncthreads();
    int i0 = (t >> 4) * 8;
    int h0 = (t & 15) * 4;
    float acc[8][4];
    #pragma unroll
    for (int a = 0; a < 8; a++)
        #pragma unroll
        for (int b = 0; b < 4; b++) acc[a][b] = 0.f;
    for (int k = 0; k < EMB; k++) {
        float wv[4];
        #pragma unroll
        for (int j = 0; j < 4; j++) wv[j] = W2s[k*HID + h0 + j];
        #pragma unroll
        for (int ii = 0; ii < 8; ii++) {
            float xv = xa1[(i0+ii)*EMB + k];
            #pragma unroll
            for (int j = 0; j < 4; j++) acc[ii][j] += xv * wv[j];
        }
    }
    #pragma unroll
    for (int ii = 0; ii < 8; ii++)
        #pragma unroll
        for (int j = 0; j < 4; j++)
            g_xa2[(i0+ii)*HID + h0 + j] = acc[ii][j] + b2[h0 + j];
}

__global__ __launch_bounds__(256) void k_xout(float* __restrict__ out) {
    __shared__ float xa[IN_DIMS*(HID+1)];
    __shared__ float es[32*HID];
    int t = threadIdx.x;
    for (int i = t; i < IN_DIMS*HID; i += 256) {
        int r = i / HID, c = i % HID;
        xa[r*(HID+1) + c] = g_xa2[i];
    }
    int nb = blockIdx.x * 32;
    for (int i = t; i < 32*HID; i += 256) es[i] = g_embP[(size_t)nb*HID + i];
    __syncthreads();
    int nl = t >> 3;
    int ib = (t & 7) * 16;
    const float* e = &es[nl*HID];
    int n = nb + nl;
    if (n >= N_NODES) return;
    for (int ii = 0; ii < 16; ii++) {
        int i = ib + ii;
        const float* w = &xa[i*(HID+1)];
        float acc = 0.f;
        #pragma unroll 8
        for (int k = 0; k < HID; k++) acc += e[k]*w[k];
        out[(size_t)n*IN_DIMS + i] = acc;
    }
}

// ================= mma.sync s_ GEMM, symmetric, staged mirror ===============
#define ROWB 272
#define BOFF 34816            // 128*272
#define SMEM_S (2*34816)      // 69632 B dynamic (also holds 128x132 f32 stage)
#define TRS 132

__device__ __forceinline__ uint32_t smem_u32(const void* p) {
    uint32_t a;
    asm("{ .reg .u64 t; cvta.to.shared.u64 t, %1; cvt.u32.u64 %0, t; }" : "=r"(a) : "l"(p));
    return a;
}
__device__ __forceinline__ void ldsm4(uint32_t addr, uint32_t& r0, uint32_t& r1,
                                      uint32_t& r2, uint32_t& r3) {
    asm volatile("ldmatrix.sync.aligned.m8n8.x4.shared.b16 {%0,%1,%2,%3}, [%4];"
                 : "=r"(r0), "=r"(r1), "=r"(r2), "=r"(r3) : "r"(addr));
}
__device__ __forceinline__ void mma16816(float c[4], uint32_t a0, uint32_t a1,
                                         uint32_t a2, uint32_t a3,
                                         uint32_t b0, uint32_t b1) {
    asm volatile(
        "mma.sync.aligned.m16n8k16.row.col.f32.bf16.bf16.f32 "
        "{%0,%1,%2,%3}, {%4,%5,%6,%7}, {%8,%9}, {%0,%1,%2,%3};"
        : "+f"(c[0]), "+f"(c[1]), "+f"(c[2]), "+f"(c[3])
        : "r"(a0), "r"(a1), "r"(a2), "r"(a3), "r"(b0), "r"(b1));
}

extern __shared__ char smem_s[];

__global__ __launch_bounds__(256) void k_s_mma(float* __restrict__ sout) {
    int b = blockIdx.x;
    int ti = 0;
    {
        int rem = b, rowlen = NT;
        while (rem >= rowlen) { rem -= rowlen; ti++; rowlen--; }
        b = rem;
    }
    int tj = ti + b;

    int t = threadIdx.x;
    int warp = t >> 5, lane = t & 31;
    int wm = warp >> 1, wn = warp & 1;
    int g = lane >> 2, tq = lane & 3;
    int q = lane >> 3, r8 = lane & 7;

    const __nv_bfloat16* gA = &g_Ebf[(size_t)ti * TILE * KS];
    const __nv_bfloat16* gB = &g_Ebf[(size_t)tj * TILE * KS];
    #pragma unroll
    for (int i = 0; i < 8; i++) {
        int v = i * 256 + t;
        int row = v >> 4;
        int c16 = v & 15;
        *(float4*)(smem_s + row*ROWB + c16*16)        = *(const float4*)(gA + row*KS + c16*8);
        *(float4*)(smem_s + BOFF + row*ROWB + c16*16) = *(const float4*)(gB + row*KS + c16*8);
    }
    __syncthreads();

    uint32_t sA = smem_u32(smem_s);
    uint32_t sB = sA + BOFF;

    uint32_t aAddr[2], bAddr[4];
    #pragma unroll
    for (int mt = 0; mt < 2; mt++)
        aAddr[mt] = sA + (uint32_t)(wm*32 + mt*16 + r8 + (q & 1)*8)*ROWB + (uint32_t)((q >> 1)*8)*2;
    #pragma unroll
    for (int n2 = 0; n2 < 4; n2++)
        bAddr[n2] = sB + (uint32_t)(wn*64 + n2*16 + r8 + (q >> 1)*8)*ROWB + (uint32_t)((q & 1)*8)*2;

    float c[2][8][4];
    #pragma unroll
    for (int mt = 0; mt < 2; mt++)
        #pragma unroll
        for (int nt = 0; nt < 8; nt++)
            #pragma unroll
            for (int rr = 0; rr < 4; rr++) c[mt][nt][rr] = 0.f;

    #pragma unroll
    for (int s = 0; s < 12; s++) {
        int pass = s >> 2;
        int kk = (s & 3) * 16;
        uint32_t ka = (uint32_t)(((pass == 1) ? 64 : 0) + kk) * 2;
        uint32_t kb = (uint32_t)(((pass == 2) ? 64 : 0) + kk) * 2;

        uint32_t a[2][4];
        #pragma unroll
        for (int mt = 0; mt < 2; mt++)
            ldsm4(aAddr[mt] + ka, a[mt][0], a[mt][1], a[mt][2], a[mt][3]);

        #pragma unroll
        for (int n2 = 0; n2 < 4; n2++) {
            uint32_t b0, b1, b2, b3;
            ldsm4(bAddr[n2] + kb, b0, b1, b2, b3);
            int nt = n2 * 2;
            mma16816(c[0][nt],   a[0][0], a[0][1], a[0][2], a[0][3], b0, b1);
            mma16816(c[1][nt],   a[1][0], a[1][1], a[1][2], a[1][3], b0, b1);
            mma16816(c[0][nt+1], a[0][0], a[0][1], a[0][2], a[0][3], b2, b3);
            mma16816(c[1][nt+1], a[1][0], a[1][1], a[1][2], a[1][3], b2, b3);
        }
    }

    // sigmoid
    #pragma unroll
    for (int mt = 0; mt < 2; mt++)
        #pragma unroll
        for (int nt = 0; nt < 8; nt++)
            #pragma unroll
            for (int rr = 0; rr < 4; rr++)
                c[mt][nt][rr] = 1.f / (1.f + __expf(-c[mt][nt][rr]));

    // normal tile: direct row-major stores
    #pragma unroll
    for (int mt = 0; mt < 2; mt++) {
        #pragma unroll
        for (int rr = 0; rr < 2; rr++) {
            int gr = ti*TILE + wm*32 + mt*16 + g + rr*8;
            if (gr >= N_NODES) continue;
            size_t obase = (size_t)gr * N_NODES;
            #pragma unroll
            for (int nt = 0; nt < 8; nt++) {
                int gc = tj*TILE + wn*64 + nt*8 + tq*2;
                if (gc < N_NODES)
                    *(float2*)&sout[obase + gc] =
                        make_float2(c[mt][nt][rr*2], c[mt][nt][rr*2 + 1]);
            }
        }
    }

    // mirror tile: stage transposed in smem, write contiguous rows
    if (ti != tj) {
        __syncthreads();
        float* tr = (float*)smem_s;
        #pragma unroll
        for (int mt = 0; mt < 2; mt++) {
            #pragma unroll
            for (int rr = 0; rr < 2; rr++) {
                int lr = wm*32 + mt*16 + g + rr*8;
                #pragma unroll
                for (int nt = 0; nt < 8; nt++) {
                    int lc = wn*64 + nt*8 + tq*2;
                    tr[lc*TRS + lr]       = c[mt][nt][rr*2];
                    tr[(lc+1)*TRS + lr]   = c[mt][nt][rr*2 + 1];
                }
            }
        }
        __syncthreads();
        int len = N_NODES - ti*TILE;       // valid columns in mirror rows
        if (len > TILE) len = TILE;
        int lr0 = lane * 4;
        #pragma unroll
        for (int rr2 = 0; rr2 < 16; rr2++) {
            int lc = warp*16 + rr2;
            int gcRow = tj*TILE + lc;
            if (gcRow < N_NODES && lr0 < len) {
                *(float4*)&sout[(size_t)gcRow*N_NODES + ti*TILE + lr0] =
                    *(float4*)&tr[lc*TRS + lr0];
            }
        }
    }
}

// ---------------- launch ----------------
extern "C" void kernel_launch(void* const* d_in, const int* in_sizes, int n_in,
                              void* d_out, int out_size) {
    const float* x       = (const float*)d_in[0];
    const int*   ei      = (const int*)d_in[1];
    const float* W_stru  = (const float*)d_in[3];
    const float* b_stru  = (const float*)d_in[4];
    const float* W_gat   = (const float*)d_in[5];
    const float* att_src = (const float*)d_in[6];
    const float* att_dst = (const float*)d_in[7];
    const float* b_gat   = (const float*)d_in[8];
    const float* W_attr1 = (const float*)d_in[9];
    const float* b_attr1 = (const float*)d_in[10];
    const float* W_attr2 = (const float*)d_in[11];
    const float* b_attr2 = (const float*)d_in[12];

    int E = in_sizes[1] / 2;
    int EN = E + N_NODES;

    float* out   = (float*)d_out;
    float* x_out = out;
    float* s_out = out + (size_t)N_NODES * IN_DIMS;

    static int attrSet = 0;
    cudaFuncSetAttribute(k_enc, cudaFuncAttributeMaxDynamicSharedMemorySize, 61440);
    cudaFuncSetAttribute(k_s_mma, cudaFuncAttributeMaxDynamicSharedMemorySize, SMEM_S);
    (void)attrSet;

    k_zero  <<<148, 256>>>();
    k_enc   <<<N_NODES / 16, 256, 61440>>>(x, W_stru, b_stru, W_gat, att_src, att_dst);
    k_edge1 <<<(EN + 255) / 256, 256>>>(ei, E);
    k_scan2 <<<1, 1024>>>();
    k_edge2 <<<(EN + 255) / 256, 256>>>(ei, E);
    k_aggr  <<<(N_NODES * 32 + 255) / 256, 256>>>(b_gat);
    k_attr1 <<<100, 256>>>(x, W_attr1);
    k_attr2 <<<1, 256>>>(b_attr1, W_attr2, b_attr2);
    k_xout  <<<(N_NODES + 31) / 32, 256>>>(x_out);
    k_s_mma <<<NT * (NT + 1) / 2, 256, SMEM_S>>>(s_out);
}